// round 1
// baseline (speedup 1.0000x reference)
#include <cuda_runtime.h>
#include <math_constants.h>

// Fused: out[b,c,y,x] = relu( p1[b,c%256,y,x] + p2[b,c%128,y,x]
//                           + p3[b,c%64,y,x] + p4[b,c%32,y,x] + ff[b,c,y,x] )
// where pK = non-overlapping maxpool of inK with kernel 2/4/8/16 respectively.
//
// One thread handles (b, y, x, c_base) and produces all 16 output channels
// c = c_base + 32*j. Every input element is read exactly once chip-wide.

__global__ __launch_bounds__(256)
void fused_ffblock_kernel(
    const float* __restrict__ in1,   // [B,256, 64, 64]
    const float* __restrict__ in2,   // [B,128,128,128]
    const float* __restrict__ in3,   // [B, 64,256,256]
    const float* __restrict__ in4,   // [B, 32,512,512]
    const float* __restrict__ ff,    // [B,512, 32, 32]
    float* __restrict__ out)         // [B,512, 32, 32]
{
    const int x  = threadIdx.x;                       // 0..31 (pooled col)
    const int y  = blockIdx.x * blockDim.y + threadIdx.y; // 0..31 (pooled row)
    const int cb = blockIdx.y;                        // 0..31 (base channel)
    const int b  = blockIdx.z;                        // 0..7

    // ---- p4: maxpool16 of in4[b, cb] over 16x16 window ----
    float p4 = -CUDART_INF_F;
    {
        const float* base = in4 + ((((size_t)b * 32 + cb) * 512 + (size_t)y * 16) * 512) + (size_t)x * 16;
        #pragma unroll
        for (int r = 0; r < 16; r++) {
            const float4* row = reinterpret_cast<const float4*>(base + (size_t)r * 512);
            #pragma unroll
            for (int k = 0; k < 4; k++) {
                float4 v = row[k];
                p4 = fmaxf(p4, fmaxf(fmaxf(v.x, v.y), fmaxf(v.z, v.w)));
            }
        }
    }

    // ---- p3: maxpool8 of in3[b, cb + 32*j] over 8x8 window, j=0..1 ----
    float p3v[2];
    #pragma unroll
    for (int j = 0; j < 2; j++) {
        const int c = cb + 32 * j;
        const float* base = in3 + ((((size_t)b * 64 + c) * 256 + (size_t)y * 8) * 256) + (size_t)x * 8;
        float m = -CUDART_INF_F;
        #pragma unroll
        for (int r = 0; r < 8; r++) {
            const float4* row = reinterpret_cast<const float4*>(base + (size_t)r * 256);
            #pragma unroll
            for (int k = 0; k < 2; k++) {
                float4 v = row[k];
                m = fmaxf(m, fmaxf(fmaxf(v.x, v.y), fmaxf(v.z, v.w)));
            }
        }
        p3v[j] = m;
    }

    // ---- p2: maxpool4 of in2[b, cb + 32*j] over 4x4 window, j=0..3 ----
    float p2v[4];
    #pragma unroll
    for (int j = 0; j < 4; j++) {
        const int c = cb + 32 * j;
        const float* base = in2 + ((((size_t)b * 128 + c) * 128 + (size_t)y * 4) * 128) + (size_t)x * 4;
        float m = -CUDART_INF_F;
        #pragma unroll
        for (int r = 0; r < 4; r++) {
            float4 v = *reinterpret_cast<const float4*>(base + (size_t)r * 128);
            m = fmaxf(m, fmaxf(fmaxf(v.x, v.y), fmaxf(v.z, v.w)));
        }
        p2v[j] = m;
    }

    // ---- p1: maxpool2 of in1[b, cb + 32*j] over 2x2 window, j=0..7 ----
    float p1v[8];
    #pragma unroll
    for (int j = 0; j < 8; j++) {
        const int c = cb + 32 * j;
        const float* base = in1 + ((((size_t)b * 256 + c) * 64 + (size_t)y * 2) * 64) + (size_t)x * 2;
        float2 r0 = *reinterpret_cast<const float2*>(base);
        float2 r1 = *reinterpret_cast<const float2*>(base + 64);
        p1v[j] = fmaxf(fmaxf(r0.x, r0.y), fmaxf(r1.x, r1.y));
    }

    // ---- combine: 16 output channels ----
    #pragma unroll
    for (int j = 0; j < 16; j++) {
        const int c = cb + 32 * j;
        const size_t o = (((size_t)b * 512 + c) * 32 + y) * 32 + x;
        float s = p1v[j & 7] + p2v[j & 3] + p3v[j & 1] + p4 + ff[o];
        out[o] = fmaxf(s, 0.0f);
    }
}

extern "C" void kernel_launch(void* const* d_in, const int* in_sizes, int n_in,
                              void* d_out, int out_size) {
    const float* in1 = (const float*)d_in[0];  // [8,256, 64, 64]
    const float* in2 = (const float*)d_in[1];  // [8,128,128,128]
    const float* in3 = (const float*)d_in[2];  // [8, 64,256,256]
    const float* in4 = (const float*)d_in[3];  // [8, 32,512,512]
    const float* ff  = (const float*)d_in[4];  // [8,512, 32, 32]
    float* out = (float*)d_out;                // [8,512, 32, 32]

    dim3 block(32, 8, 1);     // 256 threads: x = pooled col, y-chunk of pooled rows
    dim3 grid(4, 32, 8);      // 4 row-groups x 32 c_base x 8 batch = 1024 blocks

    fused_ffblock_kernel<<<grid, block>>>(in1, in2, in3, in4, ff, out);
}

// round 2
// speedup vs baseline: 1.0209x; 1.0209x over previous
#include <cuda_runtime.h>
#include <math_constants.h>

// Fused: out[b,c,y,x] = relu( p1[b,c%256,y,x] + p2[b,c%128,y,x]
//                           + p3[b,c%64,y,x] + p4[b,c%32,y,x] + ff[b,c,y,x] )
// where pK = non-overlapping maxpool of inK with kernel 2/4/8/16 respectively.
//
// One thread handles (b, y, x, c_base) and produces all 16 output channels
// c = c_base + 32*j. Every input element is read exactly once chip-wide.
//
// R2 change: 64-thread blocks (4096 blocks total) to shrink the wave-
// quantization tail that capped DRAM at 67.8%.

__global__ __launch_bounds__(64)
void fused_ffblock_kernel(
    const float* __restrict__ in1,   // [B,256, 64, 64]
    const float* __restrict__ in2,   // [B,128,128,128]
    const float* __restrict__ in3,   // [B, 64,256,256]
    const float* __restrict__ in4,   // [B, 32,512,512]
    const float* __restrict__ ff,    // [B,512, 32, 32]
    float* __restrict__ out)         // [B,512, 32, 32]
{
    const int x  = threadIdx.x;                           // 0..31 (pooled col)
    const int y  = blockIdx.x * blockDim.y + threadIdx.y; // 0..31 (pooled row)
    const int cb = blockIdx.y;                            // 0..31 (base channel)
    const int b  = blockIdx.z;                            // 0..7

    // ---- p4: maxpool16 of in4[b, cb] over 16x16 window ----
    float p4 = -CUDART_INF_F;
    {
        const float* base = in4 + ((((size_t)b * 32 + cb) * 512 + (size_t)y * 16) * 512) + (size_t)x * 16;
        #pragma unroll
        for (int r = 0; r < 16; r++) {
            const float4* row = reinterpret_cast<const float4*>(base + (size_t)r * 512);
            #pragma unroll
            for (int k = 0; k < 4; k++) {
                float4 v = row[k];
                p4 = fmaxf(p4, fmaxf(fmaxf(v.x, v.y), fmaxf(v.z, v.w)));
            }
        }
    }

    // ---- p3: maxpool8 of in3[b, cb + 32*j] over 8x8 window, j=0..1 ----
    float p3v[2];
    #pragma unroll
    for (int j = 0; j < 2; j++) {
        const int c = cb + 32 * j;
        const float* base = in3 + ((((size_t)b * 64 + c) * 256 + (size_t)y * 8) * 256) + (size_t)x * 8;
        float m = -CUDART_INF_F;
        #pragma unroll
        for (int r = 0; r < 8; r++) {
            const float4* row = reinterpret_cast<const float4*>(base + (size_t)r * 256);
            #pragma unroll
            for (int k = 0; k < 2; k++) {
                float4 v = row[k];
                m = fmaxf(m, fmaxf(fmaxf(v.x, v.y), fmaxf(v.z, v.w)));
            }
        }
        p3v[j] = m;
    }

    // ---- p2: maxpool4 of in2[b, cb + 32*j] over 4x4 window, j=0..3 ----
    float p2v[4];
    #pragma unroll
    for (int j = 0; j < 4; j++) {
        const int c = cb + 32 * j;
        const float* base = in2 + ((((size_t)b * 128 + c) * 128 + (size_t)y * 4) * 128) + (size_t)x * 4;
        float m = -CUDART_INF_F;
        #pragma unroll
        for (int r = 0; r < 4; r++) {
            float4 v = *reinterpret_cast<const float4*>(base + (size_t)r * 128);
            m = fmaxf(m, fmaxf(fmaxf(v.x, v.y), fmaxf(v.z, v.w)));
        }
        p2v[j] = m;
    }

    // ---- p1: maxpool2 of in1[b, cb + 32*j] over 2x2 window, j=0..7 ----
    float p1v[8];
    #pragma unroll
    for (int j = 0; j < 8; j++) {
        const int c = cb + 32 * j;
        const float* base = in1 + ((((size_t)b * 256 + c) * 64 + (size_t)y * 2) * 64) + (size_t)x * 2;
        float2 r0 = *reinterpret_cast<const float2*>(base);
        float2 r1 = *reinterpret_cast<const float2*>(base + 64);
        p1v[j] = fmaxf(fmaxf(r0.x, r0.y), fmaxf(r1.x, r1.y));
    }

    // ---- combine: 16 output channels ----
    #pragma unroll
    for (int j = 0; j < 16; j++) {
        const int c = cb + 32 * j;
        const size_t o = (((size_t)b * 512 + c) * 32 + y) * 32 + x;
        float s = p1v[j & 7] + p2v[j & 3] + p3v[j & 1] + p4 + ff[o];
        out[o] = fmaxf(s, 0.0f);
    }
}

extern "C" void kernel_launch(void* const* d_in, const int* in_sizes, int n_in,
                              void* d_out, int out_size) {
    const float* in1 = (const float*)d_in[0];  // [8,256, 64, 64]
    const float* in2 = (const float*)d_in[1];  // [8,128,128,128]
    const float* in3 = (const float*)d_in[2];  // [8, 64,256,256]
    const float* in4 = (const float*)d_in[3];  // [8, 32,512,512]
    const float* ff  = (const float*)d_in[4];  // [8,512, 32, 32]
    float* out = (float*)d_out;                // [8,512, 32, 32]

    dim3 block(32, 2, 1);     // 64 threads: x = pooled col, 2 pooled rows
    dim3 grid(16, 32, 8);     // 16 row-groups x 32 c_base x 8 batch = 4096 blocks

    fused_ffblock_kernel<<<grid, block>>>(in1, in2, in3, in4, ff, out);
}

// round 3
// speedup vs baseline: 1.0451x; 1.0237x over previous
#include <cuda_runtime.h>
#include <math_constants.h>

// Fused multi-scale maxpool + tile + add + relu.
// R3: lane-contiguous 512B LDG.128s (nL=4) + warp-shuffle window reduction,
// pooled maps staged in smem, to eliminate L1tex wavefront amplification
// (previous version had nL=16 strided loads throttling DRAM request supply).
//
// Block = (b, cb, yg): base channel cb in [0,32), yg covers pooled rows
// [8*yg, 8*yg+8). 256 threads = 8 warps. Every input byte read exactly once.

__global__ __launch_bounds__(256)
void fused_ffblock_kernel(
    const float* __restrict__ in1,   // [8,256, 64, 64]   k=2
    const float* __restrict__ in2,   // [8,128,128,128]   k=4
    const float* __restrict__ in3,   // [8, 64,256,256]   k=8
    const float* __restrict__ in4,   // [8, 32,512,512]   k=16
    const float* __restrict__ ff,    // [8,512, 32, 32]
    float* __restrict__ out)         // [8,512, 32, 32]
{
    const int lane = threadIdx.x & 31;
    const int warp = threadIdx.x >> 5;      // 0..7
    const int yg = blockIdx.x;               // 0..3  (pooled-row group of 8)
    const int cb = blockIdx.y;               // 0..31 (base channel)
    const int b  = blockIdx.z;               // 0..7

    __shared__ float sp4[8][32];
    __shared__ float sp3[2][8][32];
    __shared__ float sp2[4][8][32];
    __shared__ float sp1[8][8][32];

    const unsigned FULL = 0xffffffffu;

    // ---- p4: k=16, channel cb. Strip = 8 windows wide (512B rows), 16 rows.
    // 32 strips (8 pooled rows x 4 x-groups), 4 per warp.
    for (int s = warp; s < 32; s += 8) {
        const int yl = s >> 2, xg = s & 3;
        const int y = yg * 8 + yl;
        const float* base = in4 + (((size_t)(b * 32 + cb) * 512 + (size_t)y * 16) * 512)
                                + xg * 128 + lane * 4;
        float4 a = *reinterpret_cast<const float4*>(base);
        #pragma unroll
        for (int r = 1; r < 16; r++) {
            float4 v = *reinterpret_cast<const float4*>(base + (size_t)r * 512);
            a.x = fmaxf(a.x, v.x); a.y = fmaxf(a.y, v.y);
            a.z = fmaxf(a.z, v.z); a.w = fmaxf(a.w, v.w);
        }
        float m = fmaxf(fmaxf(a.x, a.y), fmaxf(a.z, a.w));
        m = fmaxf(m, __shfl_xor_sync(FULL, m, 1));
        m = fmaxf(m, __shfl_xor_sync(FULL, m, 2));
        if ((lane & 3) == 0) sp4[yl][xg * 8 + (lane >> 2)] = m;
    }

    // ---- p3: k=8, channels cb, cb+32. Strip = 16 windows (512B rows), 8 rows.
    // 32 strips (2 ch x 8 rows x 2 x-groups), 4 per warp.
    for (int s = warp; s < 32; s += 8) {
        const int j = s >> 4, rem = s & 15;
        const int yl = rem >> 1, xg = rem & 1;
        const int y = yg * 8 + yl;
        const int c = cb + 32 * j;
        const float* base = in3 + (((size_t)(b * 64 + c) * 256 + (size_t)y * 8) * 256)
                                + xg * 128 + lane * 4;
        float4 a = *reinterpret_cast<const float4*>(base);
        #pragma unroll
        for (int r = 1; r < 8; r++) {
            float4 v = *reinterpret_cast<const float4*>(base + (size_t)r * 256);
            a.x = fmaxf(a.x, v.x); a.y = fmaxf(a.y, v.y);
            a.z = fmaxf(a.z, v.z); a.w = fmaxf(a.w, v.w);
        }
        float m = fmaxf(fmaxf(a.x, a.y), fmaxf(a.z, a.w));
        m = fmaxf(m, __shfl_xor_sync(FULL, m, 1));
        if ((lane & 1) == 0) sp3[j][yl][xg * 16 + (lane >> 1)] = m;
    }

    // ---- p2: k=4, channels cb+32*{0..3}. Strip = full pooled row (32 windows),
    // 4 rows of 512B. Lane == window, no shuffle. 32 strips, 4 per warp.
    for (int s = warp; s < 32; s += 8) {
        const int j = s >> 3, yl = s & 7;
        const int y = yg * 8 + yl;
        const int c = cb + 32 * j;
        const float* base = in2 + (((size_t)(b * 128 + c) * 128 + (size_t)y * 4) * 128)
                                + lane * 4;
        float4 a = *reinterpret_cast<const float4*>(base);
        #pragma unroll
        for (int r = 1; r < 4; r++) {
            float4 v = *reinterpret_cast<const float4*>(base + (size_t)r * 128);
            a.x = fmaxf(a.x, v.x); a.y = fmaxf(a.y, v.y);
            a.z = fmaxf(a.z, v.z); a.w = fmaxf(a.w, v.w);
        }
        sp2[j][yl][lane] = fmaxf(fmaxf(a.x, a.y), fmaxf(a.z, a.w));
    }

    // ---- p1: k=2, channels cb+32*{0..7}. One LDG.128 per warp covers BOTH
    // input rows (2 x 256B contiguous). 64 strips, 8 per warp.
    for (int s = warp; s < 64; s += 8) {
        const int j = s >> 3, yl = s & 7;
        const int y = yg * 8 + yl;
        const int c = cb + 32 * j;
        const float* base = in1 + (((size_t)(b * 256 + c) * 64 + (size_t)y * 2) * 64)
                                + lane * 4;
        float4 v = *reinterpret_cast<const float4*>(base);
        float m0 = fmaxf(v.x, v.y);   // window 2*(lane%16), one row's part
        float m1 = fmaxf(v.z, v.w);   // window 2*(lane%16)+1
        m0 = fmaxf(m0, __shfl_xor_sync(FULL, m0, 16));  // combine the two rows
        m1 = fmaxf(m1, __shfl_xor_sync(FULL, m1, 16));
        if (lane < 16) {
            sp1[j][yl][2 * lane]     = m0;
            sp1[j][yl][2 * lane + 1] = m1;
        }
    }

    __syncthreads();

    // ---- combine: thread (yl, x) produces 16 output channels.
    const int x  = threadIdx.x & 31;
    const int yl = threadIdx.x >> 5;   // 0..7
    const int y  = yg * 8 + yl;

    const float v4 = sp4[yl][x];
    float v3[2], v2[4];
    #pragma unroll
    for (int j = 0; j < 2; j++) v3[j] = sp3[j][yl][x];
    #pragma unroll
    for (int j = 0; j < 4; j++) v2[j] = sp2[j][yl][x];

    #pragma unroll
    for (int j = 0; j < 16; j++) {
        const size_t o = (((size_t)(b * 512 + cb + 32 * j)) * 32 + y) * 32 + x;
        float s = sp1[j & 7][yl][x] + v2[j & 3] + v3[j & 1] + v4 + ff[o];
        out[o] = fmaxf(s, 0.0f);
    }
}

extern "C" void kernel_launch(void* const* d_in, const int* in_sizes, int n_in,
                              void* d_out, int out_size) {
    const float* in1 = (const float*)d_in[0];
    const float* in2 = (const float*)d_in[1];
    const float* in3 = (const float*)d_in[2];
    const float* in4 = (const float*)d_in[3];
    const float* ff  = (const float*)d_in[4];
    float* out = (float*)d_out;

    dim3 block(256, 1, 1);
    dim3 grid(4, 32, 8);   // yg x cb x b = 1024 blocks

    fused_ffblock_kernel<<<grid, block>>>(in1, in2, in3, in4, ff, out);
}

// round 4
// speedup vs baseline: 1.1694x; 1.1190x over previous
#include <cuda_runtime.h>
#include <math_constants.h>

// Fused multi-scale maxpool + tile + add + relu.
// R4: fully warp-autonomous. One warp = one (b, cb, pooled row y).
// Lane-contiguous 512B LDG.128 strips (nL=4), window reduction via shuffles,
// no shared memory, no __syncthreads. Every input byte read exactly once.

__global__ __launch_bounds__(128)
void fused_ffblock_kernel(
    const float* __restrict__ in1,   // [8,256, 64, 64]   k=2
    const float* __restrict__ in2,   // [8,128,128,128]   k=4
    const float* __restrict__ in3,   // [8, 64,256,256]   k=8
    const float* __restrict__ in4,   // [8, 32,512,512]   k=16
    const float* __restrict__ ff,    // [8,512, 32, 32]
    float* __restrict__ out)         // [8,512, 32, 32]
{
    const int lane = threadIdx.x & 31;
    const int warp = threadIdx.x >> 5;               // 0..3
    const int y  = blockIdx.x * 4 + warp;            // 0..31 pooled row
    const int cb = blockIdx.y;                       // 0..31 base channel
    const int b  = blockIdx.z;                       // 0..7
    const unsigned FULL = 0xffffffffu;

    // ================= p4: k=16, channel cb =================
    // Row-block = 16 input rows x 512 floats. 4 x-groups of 128 floats.
    float m4g[4];
    {
        const float* base = in4 + (((size_t)(b * 32 + cb) * 512 + (size_t)y * 16) * 512);
        #pragma unroll
        for (int xg = 0; xg < 4; xg++) {
            const float* p = base + xg * 128 + lane * 4;
            float4 a = *reinterpret_cast<const float4*>(p);
            #pragma unroll
            for (int r = 1; r < 16; r++) {
                float4 v = *reinterpret_cast<const float4*>(p + (size_t)r * 512);
                a.x = fmaxf(a.x, v.x); a.y = fmaxf(a.y, v.y);
                a.z = fmaxf(a.z, v.z); a.w = fmaxf(a.w, v.w);
            }
            float m = fmaxf(fmaxf(a.x, a.y), fmaxf(a.z, a.w));
            m = fmaxf(m, __shfl_xor_sync(FULL, m, 1));
            m = fmaxf(m, __shfl_xor_sync(FULL, m, 2));
            m4g[xg] = m;   // group (lane>>2) of xg -> window xg*8 + (lane>>2)
        }
    }
    // Gather so lane x holds window x.
    float p4v;
    {
        const int src = (lane & 7) << 2;
        float w0 = __shfl_sync(FULL, m4g[0], src);
        float w1 = __shfl_sync(FULL, m4g[1], src);
        float w2 = __shfl_sync(FULL, m4g[2], src);
        float w3 = __shfl_sync(FULL, m4g[3], src);
        p4v = (lane < 16) ? ((lane < 8) ? w0 : w1) : ((lane < 24) ? w2 : w3);
    }

    // ================= p3: k=8, channels cb, cb+32 =================
    float p3v[2];
    #pragma unroll
    for (int j = 0; j < 2; j++) {
        const int c = cb + 32 * j;
        const float* base = in3 + (((size_t)(b * 64 + c) * 256 + (size_t)y * 8) * 256);
        float m3g[2];
        #pragma unroll
        for (int xg = 0; xg < 2; xg++) {
            const float* p = base + xg * 128 + lane * 4;
            float4 a = *reinterpret_cast<const float4*>(p);
            #pragma unroll
            for (int r = 1; r < 8; r++) {
                float4 v = *reinterpret_cast<const float4*>(p + (size_t)r * 256);
                a.x = fmaxf(a.x, v.x); a.y = fmaxf(a.y, v.y);
                a.z = fmaxf(a.z, v.z); a.w = fmaxf(a.w, v.w);
            }
            float m = fmaxf(fmaxf(a.x, a.y), fmaxf(a.z, a.w));
            m = fmaxf(m, __shfl_xor_sync(FULL, m, 1));
            m3g[xg] = m;   // pair (lane>>1) -> window xg*16 + (lane>>1)
        }
        const int src = (lane & 15) << 1;
        float w0 = __shfl_sync(FULL, m3g[0], src);
        float w1 = __shfl_sync(FULL, m3g[1], src);
        p3v[j] = (lane < 16) ? w0 : w1;
    }

    // ================= p2: k=4, channels cb+32*{0..3} =================
    // Row = 128 floats; lane*4 == window lane exactly. No shuffle.
    float p2v[4];
    #pragma unroll
    for (int j = 0; j < 4; j++) {
        const int c = cb + 32 * j;
        const float* p = in2 + (((size_t)(b * 128 + c) * 128 + (size_t)y * 4) * 128)
                             + lane * 4;
        float4 a = *reinterpret_cast<const float4*>(p);
        #pragma unroll
        for (int r = 1; r < 4; r++) {
            float4 v = *reinterpret_cast<const float4*>(p + (size_t)r * 128);
            a.x = fmaxf(a.x, v.x); a.y = fmaxf(a.y, v.y);
            a.z = fmaxf(a.z, v.z); a.w = fmaxf(a.w, v.w);
        }
        p2v[j] = fmaxf(fmaxf(a.x, a.y), fmaxf(a.z, a.w));
    }

    // ================= p1: k=2, channels cb+32*{0..7} =================
    // One LDG.128 covers both input rows (2 x 256B contiguous).
    float p1v[8];
    #pragma unroll
    for (int j = 0; j < 8; j++) {
        const int c = cb + 32 * j;
        const float* p = in1 + ((size_t)(b * 256 + c) * 4096) + (size_t)y * 128
                             + lane * 4;
        float4 v = *reinterpret_cast<const float4*>(p);
        float m0 = fmaxf(v.x, v.y);   // window 2*(lane&15), this row's part
        float m1 = fmaxf(v.z, v.w);   // window 2*(lane&15)+1
        m0 = fmaxf(m0, __shfl_xor_sync(FULL, m0, 16));  // combine rows 2y,2y+1
        m1 = fmaxf(m1, __shfl_xor_sync(FULL, m1, 16));
        float w0 = __shfl_sync(FULL, m0, lane >> 1);
        float w1 = __shfl_sync(FULL, m1, lane >> 1);
        p1v[j] = (lane & 1) ? w1 : w0;
    }

    // ================= combine: 16 output channels =================
    const float base = p4v;
    #pragma unroll
    for (int j = 0; j < 16; j++) {
        const size_t o = (((size_t)(b * 512 + cb + 32 * j)) * 32 + y) * 32 + lane;
        float s = p1v[j & 7] + p2v[j & 3] + p3v[j & 1] + base + ff[o];
        out[o] = fmaxf(s, 0.0f);
    }
}

extern "C" void kernel_launch(void* const* d_in, const int* in_sizes, int n_in,
                              void* d_out, int out_size) {
    const float* in1 = (const float*)d_in[0];
    const float* in2 = (const float*)d_in[1];
    const float* in3 = (const float*)d_in[2];
    const float* in4 = (const float*)d_in[3];
    const float* ff  = (const float*)d_in[4];
    float* out = (float*)d_out;

    dim3 block(128, 1, 1);    // 4 warps, each owns one pooled row
    dim3 grid(8, 32, 8);      // y-groups x cb x b = 2048 blocks

    fused_ffblock_kernel<<<grid, block>>>(in1, in2, in3, in4, ff, out);
}